// round 14
// baseline (speedup 1.0000x reference)
#include <cuda_runtime.h>
#include <cuda_fp16.h>
#include <cstdint>

// ---------------------------------------------------------------------------
// LSTM Seq2Seq on GB300 — R14: cp.async.bulk (UBLKCP) + mbarrier SMEM pipeline.
// 4-stage ring (8KB/stage: A 4KB + B 4KB), one producer thread issues 3 bulk
// copies per stage; 8 consumer warps (2m x 4n, warp tile 32m x 16n) do
// 6 LDS.128 -> 8 MMA per stage. Layouts: A/h/x = [kt][mt][lane][16B],
// B = [s][nt][lane][16B] so every stage slice is contiguous.
// ---------------------------------------------------------------------------

#define HIDDEN   512
#define BATCH    512
#define NFEAT    32
#define LAGS     96
#define HORIZONS 24
#define NGATE    2048

#define S_L0     17            // k32 stages, K=544
#define S_L1     32            // k32 stages, K=1024

#define BPK0_BYTES (256u * S_L0 * 512u)
#define BPK1_BYTES (256u * S_L1 * 512u)
#define HPK_BYTES  (32u * 32u * 512u)     // [kt 32][mt 32][512B]
#define XPK_T      (2u * 32u * 512u)      // [ktl 2][mt 32][512B] per timestep

// ---- scratch layout (bytes) ----
#define OFF_B0    0u
#define OFF_B1    (OFF_B0 + BPK0_BYTES)
#define OFF_B2    (OFF_B1 + BPK1_BYTES)
#define OFF_B3    (OFF_B2 + BPK0_BYTES)
#define OFF_BS    (OFF_B3 + BPK1_BYTES)            // float[4*2048]
#define OFF_H0PK  (OFF_BS + 4u * 2048u * 4u)       // 2 x HPK
#define OFF_H1PK  (OFF_H0PK + 2u * HPK_BYTES)      // 2 x HPK
#define OFF_C     (OFF_H1PK + 2u * HPK_BYTES)      // float[2*512*512]
#define OFF_XPK   (OFF_C + 2u * 512u * 512u * 4u)  // 96 x XPK_T
#define OFF_DECX  (OFF_XPK + 96u * XPK_T)          // XPK_T
#define OFF_H1PL  (OFF_DECX + XPK_T)               // half[512*512]
#define SCRATCH_BYTES (OFF_H1PL + 512u * 512u * 2u)

__device__ __align__(1024) unsigned char g_scratch[SCRATCH_BYTES];

// ---------------------------------------------------------------------------
__device__ __forceinline__ uint32_t smem_u32(const void* p) {
    return (uint32_t)__cvta_generic_to_shared(p);
}
__device__ __forceinline__ void mma_f16(float* d, const uint32_t* a,
                                        uint32_t b0, uint32_t b1) {
    asm volatile(
        "mma.sync.aligned.m16n8k16.row.col.f32.f16.f16.f32 "
        "{%0,%1,%2,%3},{%4,%5,%6,%7},{%8,%9},{%0,%1,%2,%3};"
        : "+f"(d[0]), "+f"(d[1]), "+f"(d[2]), "+f"(d[3])
        : "r"(a[0]), "r"(a[1]), "r"(a[2]), "r"(a[3]), "r"(b0), "r"(b1));
}
__device__ __forceinline__ float fsigmoid(float x) { return 1.f / (1.f + __expf(-x)); }
__device__ __forceinline__ float ftanh(float x)    { return 2.f / (1.f + __expf(-2.f * x)) - 1.f; }
__device__ __forceinline__ uint32_t h2u(float a, float b) {
    __half2 h = __floats2half2_rn(a, b);
    return *(uint32_t*)&h;
}
__device__ __forceinline__ void mbar_init(uint32_t mb, uint32_t cnt) {
    asm volatile("mbarrier.init.shared.b64 [%0], %1;" :: "r"(mb), "r"(cnt) : "memory");
}
__device__ __forceinline__ void mbar_arrive(uint32_t mb) {
    asm volatile("mbarrier.arrive.shared.b64 _, [%0];" :: "r"(mb) : "memory");
}
__device__ __forceinline__ void mbar_expect_tx(uint32_t mb, uint32_t tx) {
    asm volatile("mbarrier.arrive.expect_tx.shared.b64 _, [%0], %1;"
                 :: "r"(mb), "r"(tx) : "memory");
}
__device__ __forceinline__ void mbar_wait(uint32_t mb, uint32_t parity) {
    asm volatile(
        "{\n\t.reg .pred P;\n\t"
        "W_%=:\n\t"
        "mbarrier.try_wait.parity.acquire.cta.shared::cta.b64 P, [%0], %1;\n\t"
        "@!P bra W_%=;\n\t}"
        :: "r"(mb), "r"(parity) : "memory");
}
__device__ __forceinline__ void bulk_cp(uint32_t dst, const void* src,
                                        uint32_t bytes, uint32_t mb) {
    asm volatile(
        "cp.async.bulk.shared::cta.global.mbarrier::complete_tx::bytes "
        "[%0], [%1], %2, [%3];"
        :: "r"(dst), "l"(src), "r"(bytes), "r"(mb) : "memory");
}
__device__ __forceinline__ void lds128(uint4& v, uint32_t addr) {
    asm volatile("ld.shared.v4.u32 {%0,%1,%2,%3}, [%4];"
                 : "=r"(v.x), "=r"(v.y), "=r"(v.z), "=r"(v.w) : "r"(addr));
}

// ---------------------------------------------------------------------------
// Setup (launch #1): pack B (4 layers), biases, x (96 steps), zero states.
// ---------------------------------------------------------------------------
struct WPtrs { const float* w[16]; };

__global__ void setup_all(const float* __restrict__ src, WPtrs wp)
{
    unsigned char* S = g_scratch;
    const int gs   = gridDim.x * blockDim.x;
    const int tid0 = blockIdx.x * blockDim.x + threadIdx.x;

    const uint32_t boff[4]  = {OFF_B0, OFF_B1, OFF_B2, OFF_B3};
    const int      bstg[4]  = {S_L0, S_L1, S_L0, S_L1};
    const int      indim[4] = {NFEAT, HIDDEN, NFEAT, HIDDEN};

    for (int l = 0; l < 4; ++l) {
        const float* Wih = wp.w[l * 4 + 0];
        const float* Whh = wp.w[l * 4 + 1];
        uint32_t* Bp = (uint32_t*)(S + boff[l]);
        const int stg = bstg[l], idim = indim[l];
        const int total = 256 * stg * 128;          // u32 words; layout linear
        for (int u = tid0; u < total; u += gs) {
            int q    = u & 3;
            int lane = (u >> 2) & 31;
            int nt   = (u >> 7) & 255;
            int s    = u >> 15;
            int n = nt * 8 + (lane >> 2);
            int k = s * 32 + q * 8 + 2 * (lane & 3);
            int j = n >> 2, g = n & 3;
            int row = g * HIDDEN + j;
            float v0, v1;
            if (k < idim)          v0 = Wih[row * idim + k];
            else                   v0 = Whh[row * HIDDEN + (k - idim)];
            if (k + 1 < idim)      v1 = Wih[row * idim + k + 1];
            else                   v1 = Whh[row * HIDDEN + (k + 1 - idim)];
            Bp[u] = h2u(v0, v1);
        }
        const float* bih = wp.w[l * 4 + 2];
        const float* bhh = wp.w[l * 4 + 3];
        float* BS = (float*)(S + OFF_BS);
        for (int n = tid0; n < NGATE; n += gs) {
            int j = n >> 2, g = n & 3;
            BS[l * NGATE + n] = bih[g * HIDDEN + j] + bhh[g * HIDDEN + j];
        }
    }

    {   // x fragment packing: [t][ktl 2][mt 32][lane][q]  (linear in u)
        uint32_t* Xp = (uint32_t*)(S + OFF_XPK);
        const int total = LAGS * 2 * 32 * 128;
        for (int u = tid0; u < total; u += gs) {
            int q    = u & 3;
            int lane = (u >> 2) & 31;
            int mt   = (u >> 7) & 31;
            int ktl  = (u >> 12) & 1;
            int t    = u >> 13;
            int m = mt * 16 + (q & 1) * 8 + (lane >> 2);
            int k = ktl * 16 + (q >> 1) * 8 + 2 * (lane & 3);
            float v0 = src[m * (LAGS * NFEAT) + t * NFEAT + k];
            float v1 = src[m * (LAGS * NFEAT) + t * NFEAT + k + 1];
            Xp[u] = h2u(v0, v1);
        }
    }

    {   // zero h-packed (4 buffers), c, h1plain
        uint32_t* Z = (uint32_t*)(S + OFF_H0PK);
        int total = (4 * HPK_BYTES + 2 * 512 * 512 * 4) / 4;
        for (int i = tid0; i < total; i += gs) Z[i] = 0;
        uint32_t* P = (uint32_t*)(S + OFF_H1PL);
        for (int i = tid0; i < 512 * 512 * 2 / 4; i += gs) P[i] = 0;
    }
}

// launch #2: initial decx (packed [ktl][mt]) from src[:, 95, :]
__global__ void init_decx_pk(const float* __restrict__ src)
{
    uint32_t* Dp = (uint32_t*)(g_scratch + OFF_DECX);
    int u = blockIdx.x * blockDim.x + threadIdx.x;
    if (u >= 2 * 32 * 128) return;
    int q    = u & 3;
    int lane = (u >> 2) & 31;
    int mt   = (u >> 7) & 31;
    int ktl  = (u >> 12) & 1;
    int m = mt * 16 + (q & 1) * 8 + (lane >> 2);
    int k = ktl * 16 + (q >> 1) * 8 + 2 * (lane & 3);
    float v0 = src[m * (LAGS * NFEAT) + (LAGS - 1) * NFEAT + k];
    float v1 = src[m * (LAGS * NFEAT) + (LAGS - 1) * NFEAT + k + 1];
    Dp[u] = h2u(v0, v1);
}

// ---------------------------------------------------------------------------
// Bulk-pipelined GEMM + fused LSTM cell.
// grid(32, 8): x = n64-tile, y = m64-tile. 256 threads = 8 warps (2m x 4n),
// warp tile 32m x 16n. SMEM ring: 4 stages x (A 4KB | B 4KB) + mbarriers.
// ---------------------------------------------------------------------------
#define RING 4
#define STG_B 8192

template <int S, int XKT, bool WPLAIN>
__global__ __launch_bounds__(256, 2)
void lstm_step_bulk(const unsigned char* __restrict__ xp,  // [kt XKT][mt 32][512B]
                    const unsigned char* __restrict__ hp,  // [kt 32][mt 32][512B]
                    const unsigned char* __restrict__ Bp,  // [s][nt 256][512B]
                    const float* __restrict__ bs,
                    float* __restrict__ cst,
                    unsigned char* __restrict__ hop,       // packed h out [kt][mt]
                    __half* __restrict__ hplain)
{
    __shared__ __align__(128) unsigned char smbuf[RING * STG_B + 64];

    const int tid  = threadIdx.x;
    const int w    = tid >> 5, lane = tid & 31;
    const int mgrp = w >> 2, ngrp = w & 3;
    const int mtb4 = blockIdx.y * 4;
    const int ntb8 = blockIdx.x * 8;

    const uint32_t sb = smem_u32(smbuf);
    const uint32_t mb_full  = sb + RING * STG_B;
    const uint32_t mb_empty = mb_full + 32;

    if (tid == 0) {
#pragma unroll
        for (int r = 0; r < RING; ++r) {
            mbar_init(mb_full  + r * 8, 1);
            mbar_init(mb_empty + r * 8, 8);
        }
    }
    __syncthreads();

    auto produce = [&](int ps) {
        const int r = ps & (RING - 1);
        const uint32_t dst = sb + r * STG_B;
        const uint32_t mb  = mb_full + r * 8;
        mbar_expect_tx(mb, STG_B);
        const int kt0 = 2 * ps;
        const unsigned char* ab;
        int ktc;
        if (kt0 < XKT) { ab = xp; ktc = kt0; }
        else           { ab = hp; ktc = kt0 - XKT; }
        const unsigned char* a0 = ab + ((size_t)ktc * 32 + mtb4) * 512;
        bulk_cp(dst,        a0,          2048, mb);
        bulk_cp(dst + 2048, a0 + 16384,  2048, mb);
        bulk_cp(dst + 4096, Bp + ((size_t)ps * 256 + ntb8) * 512, 4096, mb);
    };

    if (tid == 0) {
#pragma unroll
        for (int ps = 0; ps < RING && ps < S; ++ps) produce(ps);
    }

    float acc[2][2][4];
#pragma unroll
    for (int i = 0; i < 2; ++i)
#pragma unroll
        for (int nf = 0; nf < 2; ++nf)
#pragma unroll
            for (int q = 0; q < 4; ++q) acc[i][nf][q] = 0.f;

#pragma unroll 4
    for (int s = 0; s < S; ++s) {
        const int r = s & (RING - 1);
        mbar_wait(mb_full + r * 8, (s >> 2) & 1);

        const uint32_t stg = sb + r * STG_B;
        uint4 a[2][2], b[2];
#pragma unroll
        for (int i = 0; i < 2; ++i)
#pragma unroll
            for (int p = 0; p < 2; ++p)
                lds128(a[i][p], stg + p * 2048 + (mgrp * 2 + i) * 512 + lane * 16);
#pragma unroll
        for (int j = 0; j < 2; ++j)
            lds128(b[j], stg + 4096 + (ngrp * 2 + j) * 512 + lane * 16);

#pragma unroll
        for (int i = 0; i < 2; ++i)
#pragma unroll
            for (int j = 0; j < 2; ++j) {
                mma_f16(acc[i][j], (const uint32_t*)&a[i][0], b[j].x, b[j].y);
                mma_f16(acc[i][j], (const uint32_t*)&a[i][1], b[j].z, b[j].w);
            }

        __syncwarp();
        if (lane == 0) mbar_arrive(mb_empty + r * 8);

        if (tid == 0 && s + RING < S) {
            mbar_wait(mb_empty + r * 8, (s >> 2) & 1);
            produce(s + RING);
        }
    }

    // ---- epilogue: accs -> smem z [64][68] -> fused cell (R10 form) ----
    __syncthreads();
    float* zs = (float*)smbuf;                 // alias ring buffer (done with it)
#pragma unroll
    for (int i = 0; i < 2; ++i)
#pragma unroll
        for (int nf = 0; nf < 2; ++nf) {
            int r = mgrp * 32 + i * 16 + (lane >> 2);
            int c = ngrp * 16 + nf * 8 + 2 * (lane & 3);
            *(float2*)&zs[r * 68 + c]       = make_float2(acc[i][nf][0], acc[i][nf][1]);
            *(float2*)&zs[(r + 8) * 68 + c] = make_float2(acc[i][nf][2], acc[i][nf][3]);
        }
    __syncthreads();

    {
        const int row = tid >> 2;
        const int grp = tid & 3;
        const int bg  = blockIdx.y * 64 + row;
        const int j0  = blockIdx.x * 16 + grp * 4;
        const int n0  = blockIdx.x * 64 + grp * 16;

        const float* zrow = &zs[row * 68 + grp * 16];
        float4 cA = *(const float4*)&cst[bg * HIDDEN + j0];
        float cOld[4] = {cA.x, cA.y, cA.z, cA.w};
        float hv[4], cN[4];
#pragma unroll
        for (int q = 0; q < 4; ++q) {
            float4 z4 = *(const float4*)&zrow[q * 4];
            float4 b4 = *(const float4*)&bs[n0 + q * 4];
            float zi = z4.x + b4.x;
            float zf = z4.y + b4.y;
            float zg = z4.z + b4.z;
            float zo = z4.w + b4.w;
            float cn = fsigmoid(zf) * cOld[q] + fsigmoid(zi) * ftanh(zg);
            cN[q] = cn;
            hv[q] = fsigmoid(zo) * ftanh(cn);
        }
        *(float4*)&cst[bg * HIDDEN + j0] = make_float4(cN[0], cN[1], cN[2], cN[3]);

        // packed h store, [kt][mt] layout
        {
            int kt = j0 >> 4, kkb = j0 & 15;
            int mt = bg >> 4, r = bg & 15;
            int q  = ((r >> 3) & 1) + ((kkb >> 3) & 1) * 2;
            int l0 = ((r & 7) << 2) + ((kkb & 7) >> 1);
            unsigned char* base = hop + (((size_t)kt * 32 + mt) * 32 + l0) * 16 + q * 4;
            *(uint32_t*)base        = h2u(hv[0], hv[1]);
            *(uint32_t*)(base + 16) = h2u(hv[2], hv[3]);
        }
        if (WPLAIN) {
            __half2 p0 = __floats2half2_rn(hv[0], hv[1]);
            __half2 p1 = __floats2half2_rn(hv[2], hv[3]);
            *(uint2*)&hplain[bg * HIDDEN + j0] =
                make_uint2(*(uint32_t*)&p0, *(uint32_t*)&p1);
        }
    }
}

// ---------------------------------------------------------------------------
// Decoder heads: out[b][t] = h1·fc1 + b1 ; decx_packed = h1·fc4^T + b4
// ---------------------------------------------------------------------------
__global__ __launch_bounds__(256)
void dec_fc(const __half* __restrict__ h1,
            const float* __restrict__ fc1_w, const float* __restrict__ fc1_b,
            const float* __restrict__ fc4_w, const float* __restrict__ fc4_b,
            float* __restrict__ out, int t)
{
    unsigned char* Dp = g_scratch + OFF_DECX;
    __shared__ float sh[HIDDEN];
    const int b = blockIdx.x;
    for (int i = threadIdx.x; i < HIDDEN; i += blockDim.x)
        sh[i] = __half2float(h1[b * HIDDEN + i]);
    __syncthreads();

    const int warp = threadIdx.x >> 5;
    const int lane = threadIdx.x & 31;
    for (int o = warp; o < 1 + NFEAT; o += 8) {
        const float* w = (o == 0) ? fc1_w : (fc4_w + (o - 1) * HIDDEN);
        float s = 0.f;
#pragma unroll 4
        for (int k = lane; k < HIDDEN; k += 32) s += sh[k] * w[k];
#pragma unroll
        for (int off = 16; off; off >>= 1) s += __shfl_down_sync(0xffffffffu, s, off);
        if (lane == 0) {
            if (o == 0) {
                out[b * HORIZONS + t] = s + fc1_b[0];
            } else {
                int f = o - 1;
                float v = s + fc4_b[f];
                int ktl = f >> 4, kk = f & 15;
                int mt = b >> 4, r = b & 15;
                int q  = ((r >> 3) & 1) + ((kk >> 3) & 1) * 2;
                int l0 = ((r & 7) << 2) + ((kk & 7) >> 1);
                unsigned char* addr = Dp + (((size_t)ktl * 32 + mt) * 32 + l0) * 16
                                      + q * 4 + (kk & 1) * 2;
                *(__half*)addr = __float2half_rn(v);
            }
        }
    }
}

// ---------------------------------------------------------------------------
extern "C" void kernel_launch(void* const* d_in, const int* in_sizes, int n_in,
                              void* d_out, int out_size)
{
    const int wb = (in_sizes[2] == 1) ? 3 : 2;

    const float* src = (const float*)d_in[0];
    WPtrs wp;
    for (int i = 0; i < 16; i++) wp.w[i] = (const float*)d_in[wb + i];
    const float* fc1_w = (const float*)d_in[wb + 16];
    const float* fc1_b = (const float*)d_in[wb + 17];
    const float* fc4_w = (const float*)d_in[wb + 18];
    const float* fc4_b = (const float*)d_in[wb + 19];
    float* out = (float*)d_out;

    unsigned char* S = nullptr;
    cudaGetSymbolAddress((void**)&S, g_scratch);

    unsigned char* B0 = S + OFF_B0;
    unsigned char* B1 = S + OFF_B1;
    unsigned char* B2 = S + OFF_B2;
    unsigned char* B3 = S + OFF_B3;
    float* BS = (float*)(S + OFF_BS);
    unsigned char* H0PK[2] = {S + OFF_H0PK, S + OFF_H0PK + HPK_BYTES};
    unsigned char* H1PK[2] = {S + OFF_H1PK, S + OFF_H1PK + HPK_BYTES};
    float* C0 = (float*)(S + OFF_C);
    float* C1 = C0 + 512 * 512;
    unsigned char* XPK  = S + OFF_XPK;
    unsigned char* DECX = S + OFF_DECX;
    __half* H1PL = (__half*)(S + OFF_H1PL);

    // launch #1, #2  ->  ncu -s 5 lands on launch #6 = l1(t=1)
    setup_all<<<1024, 256>>>(src, wp);
    init_decx_pk<<<(2 * 32 * 128 + 255) / 256, 256>>>(src);

    dim3 grid(32, 8);   // 256 CTAs, 256 threads each

    for (int t = 0; t < LAGS; t++) {
        lstm_step_bulk<S_L0, 2, false><<<grid, 256>>>(
            XPK + (size_t)t * XPK_T, H0PK[t & 1], B0, BS + 0 * NGATE,
            C0, H0PK[(t + 1) & 1], nullptr);
        lstm_step_bulk<S_L1, 32, false><<<grid, 256>>>(
            H0PK[(t + 1) & 1], H1PK[t & 1], B1, BS + 1 * NGATE,
            C1, H1PK[(t + 1) & 1], nullptr);
    }

    for (int tt = 0; tt < HORIZONS; tt++) {
        int t = LAGS + tt;
        lstm_step_bulk<S_L0, 2, false><<<grid, 256>>>(
            DECX, H0PK[t & 1], B2, BS + 2 * NGATE,
            C0, H0PK[(t + 1) & 1], nullptr);
        lstm_step_bulk<S_L1, 32, true><<<grid, 256>>>(
            H0PK[(t + 1) & 1], H1PK[t & 1], B3, BS + 3 * NGATE,
            C1, H1PK[(t + 1) & 1], H1PL);
        dec_fc<<<BATCH, 256>>>(H1PL, fc1_w, fc1_b, fc4_w, fc4_b, out, tt);
    }
}